// round 12
// baseline (speedup 1.0000x reference)
#include <cuda_runtime.h>
#include <math.h>

#define HH 7            // heads per state (Fano plane points)
#define LL 7            // Fano lines
#define TPB 256         // 8 warps
#define WPB 8
#define SPW 4           // states per warp (28 active lanes)
#define SPB (WPB * SPW) // 32 states per block
#define RPW (SPW * 7)   // 28 rows per warp
#define RPB (SPB * 7)   // 224 rows per block
#define SQ_WSTRIDE 228  // per-warp smem floats: 4 states x 57 (odd pad, proven)

// Fano lines (0-based), packed 4 bits per line (validated R9-R11):
#define LI_PACK 0x02211000u
#define LJ_PACK 0x04343531u
#define LK_PACK 0x05665642u

__device__ double g_qerr_sum = 0.0;
__device__ double g_fano_sum = 0.0;
__device__ unsigned g_count = 0;

// Reduce two fp32 values across the block (256 thr = 8 warps) in one pass.
__inline__ __device__ void blockReduce2F(float v1, float v2, float& o1, float& o2) {
    __shared__ float s1[8], s2[8];
    int lane = threadIdx.x & 31;
    int wid  = threadIdx.x >> 5;
    #pragma unroll
    for (int o = 16; o > 0; o >>= 1) {
        v1 += __shfl_down_sync(0xffffffffu, v1, o);
        v2 += __shfl_down_sync(0xffffffffu, v2, o);
    }
    if (lane == 0) { s1[wid] = v1; s2[wid] = v2; }
    __syncthreads();
    if (wid == 0) {
        v1 = (lane < WPB) ? s1[lane] : 0.0f;
        v2 = (lane < WPB) ? s2[lane] : 0.0f;
        #pragma unroll
        for (int o = 4; o > 0; o >>= 1) {
            v1 += __shfl_down_sync(0xffffffffu, v1, o);
            v2 += __shfl_down_sync(0xffffffffu, v2, o);
        }
        o1 = v1; o2 = v2;
    }
}

// Branchless closed-form nearest E8 root. All 240 roots have |r|^2=2, so
// nearest = argmax<residual,root>, computed analytically from root structure.
__device__ __forceinline__ int e8_nearest(const float r[8], float root_out[8]) {
    float a[8];
    unsigned smask = 0;
    #pragma unroll
    for (int k = 0; k < 8; k++) {
        smask |= (__float_as_uint(r[k]) >> 31) << k;
        a[k] = fabsf(r[k]);
    }

    // --- argmax (first index wins ties) ---
    float m01 = fmaxf(a[0], a[1]);  int i01 = (a[1] > a[0]) ? 1 : 0;
    float m23 = fmaxf(a[2], a[3]);  int i23 = (a[3] > a[2]) ? 3 : 2;
    float m45 = fmaxf(a[4], a[5]);  int i45 = (a[5] > a[4]) ? 5 : 4;
    float m67 = fmaxf(a[6], a[7]);  int i67 = (a[7] > a[6]) ? 7 : 6;
    float mA  = fmaxf(m01, m23);    int iA  = (m23 > m01) ? i23 : i01;
    float mB  = fmaxf(m45, m67);    int iB  = (m67 > m45) ? i67 : i45;
    float a1v = fmaxf(mA, mB);      int i1  = (mB > mA) ? iB : iA;

    // --- second argmax over k != i1 ---
    float b[8];
    #pragma unroll
    for (int k = 0; k < 8; k++) b[k] = (k == i1) ? -1.0f : a[k];
    float n01 = fmaxf(b[0], b[1]);  int j01 = (b[1] > b[0]) ? 1 : 0;
    float n23 = fmaxf(b[2], b[3]);  int j23 = (b[3] > b[2]) ? 3 : 2;
    float n45 = fmaxf(b[4], b[5]);  int j45 = (b[5] > b[4]) ? 5 : 4;
    float n67 = fmaxf(b[6], b[7]);  int j67 = (b[7] > b[6]) ? 7 : 6;
    float nA  = fmaxf(n01, n23);    int jA  = (n23 > n01) ? j23 : j01;
    float nB  = fmaxf(n45, n67);    int jB  = (n67 > n45) ? j67 : j45;
    float a2v = fmaxf(nA, nB);      int i2  = (nB > nA) ? jB : jA;

    // --- argmin (first index wins ties) ---
    float p01 = fminf(a[0], a[1]);  int q01 = (a[1] < a[0]) ? 1 : 0;
    float p23 = fminf(a[2], a[3]);  int q23 = (a[3] < a[2]) ? 3 : 2;
    float p45 = fminf(a[4], a[5]);  int q45 = (a[5] < a[4]) ? 5 : 4;
    float p67 = fminf(a[6], a[7]);  int q67 = (a[7] < a[6]) ? 7 : 6;
    float pA  = fminf(p01, p23);    int qA  = (p23 < p01) ? q23 : q01;
    float pB  = fminf(p45, p67);    int qB  = (p67 < p45) ? q67 : q45;
    float amin = fminf(pA, pB);     int imin = (pB < pA) ? qB : qA;

    float s = ((a[0] + a[1]) + (a[2] + a[3])) + ((a[4] + a[5]) + (a[6] + a[7]));
    unsigned par = __popc(smask) & 1u;

    float pairDot = a1v + a2v;
    float halfDot = 0.5f * s - (par ? amin : 0.0f);
    bool usePair = pairDot >= halfDot;

    int i = min(i1, i2), j = max(i1, i2);
    int pidx = i * 7 - ((i * (i - 1)) >> 1) + (j - i - 1);
    unsigned si = (smask >> i) & 1u, sj = (smask >> j) & 1u;
    int idxPair = 4 * pidx + 2 * (int)si + (int)sj;

    unsigned rmask = __brev(smask) >> 24;
    unsigned hv = rmask ^ (par << (7 - imin));
    int idxHalf = 112 + (int)(hv >> 1);

    #pragma unroll
    for (int k = 0; k < 8; k++) {
        float sgn = ((smask >> k) & 1u) ? -1.0f : 1.0f;
        float pairRoot = ((k == i1) | (k == i2)) ? sgn : 0.0f;
        float halfRoot = ((hv >> (7 - k)) & 1u) ? -0.5f : 0.5f;
        root_out[k] = usePair ? pairRoot : halfRoot;
    }
    return usePair ? idxPair : idxHalf;
}

__device__ __forceinline__ void qmul(const float q[4], const float p[4], float o[4]) {
    o[0] = q[0]*p[0] - q[1]*p[1] - q[2]*p[2] - q[3]*p[3];
    o[1] = q[0]*p[1] + q[1]*p[0] + q[2]*p[3] - q[3]*p[2];
    o[2] = q[0]*p[2] - q[1]*p[3] + q[2]*p[0] + q[3]*p[1];
    o[3] = q[0]*p[3] + q[1]*p[2] - q[2]*p[1] + q[3]*p[0];
}

__global__ void __launch_bounds__(TPB, 8)
fused_kernel(const float* __restrict__ states,
             float* __restrict__ out,
             float* __restrict__ prod_out,
             float* __restrict__ align_out,
             float* __restrict__ qerr_out,
             float* __restrict__ fano_out,
             int nrows, size_t off_idx,
             double inv_nq, double inv_nf,
             unsigned nblocks) {
    __shared__ float sq[WPB * SQ_WSTRIDE];   // 7296 B

    int tid = threadIdx.x;
    int w   = tid >> 5;
    int lam = tid & 31;
    bool active = lam < RPW;                 // lanes 0..27 do compute
    int sl  = lam / 7;                       // state within warp (0..3)
    int sub = lam - sl * 7;                  // head / line (0..6)
    int rw0 = blockIdx.x * RPB + w * RPW;    // warp's first global row
    int row = rw0 + lam;
    float* swq = sq + w * SQ_WSTRIDE;        // warp's private smem region

    bool full = (blockIdx.x * RPB + RPB) <= nrows;  // all warp rows valid
    bool valid = active && (full || row < nrows);

    float qe = 0.0f, fsv = 0.0f;
    float pr[8] = {0.f,0.f,0.f,0.f,0.f,0.f,0.f,0.f};

    // ---------------- Phase 1: residual E8 quantization ----------------
    if (valid) {
        float x[8];
        const float4* p = reinterpret_cast<const float4*>(states + (size_t)row * 8);
        float4 v0 = p[0], v1 = p[1];
        x[0] = v0.x; x[1] = v0.y; x[2] = v0.z; x[3] = v0.w;
        x[4] = v1.x; x[5] = v1.y; x[6] = v1.z; x[7] = v1.w;

        float res[8], root[8], qsum[8];
        #pragma unroll
        for (int k = 0; k < 8; k++) res[k] = x[k];

        int idx0 = e8_nearest(res, root);
        #pragma unroll
        for (int k = 0; k < 8; k++) { qsum[k] = root[k]; res[k] = x[k] - qsum[k]; }

        int idx1 = e8_nearest(res, root);
        #pragma unroll
        for (int k = 0; k < 8; k++) {
            qsum[k] += root[k];
            float d = x[k] - qsum[k];
            qe += d * d;
        }

        float* sp = swq + sl * 57 + sub * 8;
        #pragma unroll
        for (int k = 0; k < 8; k++) sp[k] = qsum[k];

        out[off_idx + row]                 = (float)idx0;
        out[off_idx + (size_t)nrows + row] = (float)idx1;
    }
    __syncwarp();

    // ------- Coalesced q writeout (warp-local, dense float4) -------------
    {
        float4* qout = reinterpret_cast<float4*>(out) + (size_t)rw0 * 2;
        #pragma unroll
        for (int it = 0; it < 2; it++) {
            int slot = lam + it * 32;            // 56 slots per warp
            if (slot < RPW * 2 && (full || (rw0 + (slot >> 1)) < nrows)) {
                int rl = slot >> 1;
                int st = rl / 7;
                int h  = rl - st * 7;
                int k0 = (slot & 1) << 2;
                const float* sp = swq + st * 57 + h * 8 + k0;
                qout[slot] = make_float4(sp[0], sp[1], sp[2], sp[3]);
            }
        }
    }

    // ---------------- Phase 2: Fano octonion alignment -------------------
    if (valid) {
        int sh = sub * 4;
        int hi = (int)((LI_PACK >> sh) & 7u);
        int hj = (int)((LJ_PACK >> sh) & 7u);
        int hk = (int)((LK_PACK >> sh) & 7u);
        const float* base = swq + sl * 57;
        const float* av = base + hi * 8;
        const float* bv = base + hj * 8;
        const float* cv = base + hk * 8;

        float aq[4] = {av[0], av[1], av[2], av[3]};
        float bq[4] = {av[4], av[5], av[6], av[7]};
        float cq[4] = {bv[0], bv[1], bv[2], bv[3]};
        float dq[4] = {bv[4], bv[5], bv[6], bv[7]};
        float dconj[4] = {dq[0], -dq[1], -dq[2], -dq[3]};
        float cconj[4] = {cq[0], -cq[1], -cq[2], -cq[3]};

        float t1[4], t2[4], t3[4], t4[4];
        qmul(aq, cq, t1);
        qmul(dconj, bq, t2);
        qmul(dq, aq, t3);
        qmul(bq, cconj, t4);

        float dot = 0.0f, np2 = 0.0f, nc2 = 0.0f;
        #pragma unroll
        for (int k = 0; k < 4; k++) {
            float plo = t1[k] - t2[k];
            float phi = t3[k] + t4[k];
            float clo = cv[k], chi = cv[4 + k];
            dot += plo * clo + phi * chi;
            np2 += plo * plo + phi * phi;
            nc2 += clo * clo + chi * chi;
            pr[k]     = plo;
            pr[4 + k] = phi;
        }
        float align = dot * rsqrtf(fmaxf(np2 * nc2, 1e-16f));
        align_out[row] = align;

        float ac = fminf(fmaxf(align, -1.0f), 1.0f);
        fsv = 1.0f - ac;
    }

    // handoff pr[0..2] from lane+1 via shuffle (all lanes participate)
    float nb0 = __shfl_down_sync(0xffffffffu, pr[0], 1);
    float nb1 = __shfl_down_sync(0xffffffffu, pr[1], 1);
    float nb2 = __shfl_down_sync(0xffffffffu, pr[2], 1);

    // ------- Products writeout (warp-local; gp+3 is 16B aligned) ---------
    {
        float* gp = prod_out + (size_t)rw0 * 8;
        if (full) {
            float4* g4 = reinterpret_cast<float4*>(gp + 3);
            if (active)
                g4[2 * lam] = make_float4(pr[3], pr[4], pr[5], pr[6]);
            if (lam < RPW - 1)
                g4[2 * lam + 1] = make_float4(pr[7], nb0, nb1, nb2);
            if (lam == 0) { gp[0] = pr[0]; gp[1] = pr[1]; gp[2] = pr[2]; }
            if (lam == RPW - 1) gp[RPW * 8 - 1] = pr[7];
        } else if (valid) {
            float* pw = gp + lam * 8;
            #pragma unroll
            for (int k = 0; k < 8; k++) pw[k] = pr[k];
        }
    }

    // ---------------- Reduction + last-block finalize ----------------
    float bq_, bf_;
    blockReduce2F(qe, fsv, bq_, bf_);

    __shared__ bool amLast;
    if (tid == 0) {
        atomicAdd(&g_qerr_sum, (double)bq_);
        atomicAdd(&g_fano_sum, (double)bf_);
        __threadfence();
        unsigned done = atomicAdd(&g_count, 1u);
        amLast = (done == nblocks - 1);
    }
    __syncthreads();
    if (amLast && tid == 0) {
        double tq = *((volatile double*)&g_qerr_sum);
        double tf = *((volatile double*)&g_fano_sum);
        *qerr_out = (float)(tq * inv_nq);
        double fl = tf * inv_nf * 0.5;
        if (fl < 0.0) fl = 0.0;
        if (fl > 1.0) fl = 1.0;
        *fano_out = (float)fl;
        g_qerr_sum = 0.0;
        g_fano_sum = 0.0;
        g_count = 0;
    }
}

extern "C" void kernel_launch(void* const* d_in, const int* in_sizes, int n_in,
                              void* d_out, int out_size) {
    const float* states = (const float*)d_in[0];
    // d_in[1] = roots; d_in[2..4] = fano line indices (fixed constants, baked in)

    int B = in_sizes[0] / (HH * 8);      // 65536
    int nrows = B * HH;                  // 458752 = 224 * 2048

    float* out = (float*)d_out;
    size_t off_idx   = (size_t)nrows * 8;                 // quantized_ste
    size_t off_qerr  = off_idx + 2 * (size_t)nrows;       // indices (2, B, H)
    size_t off_prod  = off_qerr + 1;                      // q_err scalar
    size_t off_align = off_prod + (size_t)B * LL * 8;     // products (B, L, 8)
    size_t off_fano  = off_align + (size_t)B * LL;        // alignments (B, L)

    unsigned nblocks = (unsigned)((nrows + RPB - 1) / RPB);   // 2048

    fused_kernel<<<nblocks, TPB>>>(states, out,
                                   out + off_prod, out + off_align,
                                   out + off_qerr, out + off_fano,
                                   nrows, off_idx,
                                   1.0 / ((double)nrows * 8.0),
                                   1.0 / ((double)B * (double)LL),
                                   nblocks);
}

// round 13
// speedup vs baseline: 1.1740x; 1.1740x over previous
#include <cuda_runtime.h>
#include <math.h>

#define HH 7            // heads per state
#define LL 7            // Fano lines
#define BPB 64          // states per block
#define TPB 224         // threads; each thread handles rows tid and tid+224
#define RPB (BPB * 7)   // 448 rows per block
#define SQ_STRIDE 57    // 7*8 floats per state +1 pad (proven conflict-free)

// Fano lines (0-based), packed 4 bits per line (validated R9-R12):
#define LI_PACK 0x02211000u
#define LJ_PACK 0x04343531u
#define LK_PACK 0x05665642u

__device__ double g_qerr_sum = 0.0;
__device__ double g_fano_sum = 0.0;
__device__ unsigned g_count = 0;

// Reduce two fp32 values across the block (224 thr = 7 warps) in one pass.
__inline__ __device__ void blockReduce2F(float v1, float v2, float& o1, float& o2) {
    __shared__ float s1[8], s2[8];
    int lane = threadIdx.x & 31;
    int wid  = threadIdx.x >> 5;
    #pragma unroll
    for (int o = 16; o > 0; o >>= 1) {
        v1 += __shfl_down_sync(0xffffffffu, v1, o);
        v2 += __shfl_down_sync(0xffffffffu, v2, o);
    }
    if (lane == 0) { s1[wid] = v1; s2[wid] = v2; }
    __syncthreads();
    if (wid == 0) {
        v1 = (lane < (TPB >> 5)) ? s1[lane] : 0.0f;
        v2 = (lane < (TPB >> 5)) ? s2[lane] : 0.0f;
        #pragma unroll
        for (int o = 4; o > 0; o >>= 1) {
            v1 += __shfl_down_sync(0xffffffffu, v1, o);
            v2 += __shfl_down_sync(0xffffffffu, v2, o);
        }
        o1 = v1; o2 = v2;
    }
}

// Branchless closed-form nearest E8 root (argmax<residual,root>, |r|^2=2).
__device__ __forceinline__ int e8_nearest(const float r[8], float root_out[8]) {
    float a[8];
    unsigned smask = 0;
    #pragma unroll
    for (int k = 0; k < 8; k++) {
        smask |= (__float_as_uint(r[k]) >> 31) << k;
        a[k] = fabsf(r[k]);
    }

    float m01 = fmaxf(a[0], a[1]);  int i01 = (a[1] > a[0]) ? 1 : 0;
    float m23 = fmaxf(a[2], a[3]);  int i23 = (a[3] > a[2]) ? 3 : 2;
    float m45 = fmaxf(a[4], a[5]);  int i45 = (a[5] > a[4]) ? 5 : 4;
    float m67 = fmaxf(a[6], a[7]);  int i67 = (a[7] > a[6]) ? 7 : 6;
    float mA  = fmaxf(m01, m23);    int iA  = (m23 > m01) ? i23 : i01;
    float mB  = fmaxf(m45, m67);    int iB  = (m67 > m45) ? i67 : i45;
    float a1v = fmaxf(mA, mB);      int i1  = (mB > mA) ? iB : iA;

    float b[8];
    #pragma unroll
    for (int k = 0; k < 8; k++) b[k] = (k == i1) ? -1.0f : a[k];
    float n01 = fmaxf(b[0], b[1]);  int j01 = (b[1] > b[0]) ? 1 : 0;
    float n23 = fmaxf(b[2], b[3]);  int j23 = (b[3] > b[2]) ? 3 : 2;
    float n45 = fmaxf(b[4], b[5]);  int j45 = (b[5] > b[4]) ? 5 : 4;
    float n67 = fmaxf(b[6], b[7]);  int j67 = (b[7] > b[6]) ? 7 : 6;
    float nA  = fmaxf(n01, n23);    int jA  = (n23 > n01) ? j23 : j01;
    float nB  = fmaxf(n45, n67);    int jB  = (n67 > n45) ? j67 : j45;
    float a2v = fmaxf(nA, nB);      int i2  = (nB > nA) ? jB : jA;

    float p01 = fminf(a[0], a[1]);  int q01 = (a[1] < a[0]) ? 1 : 0;
    float p23 = fminf(a[2], a[3]);  int q23 = (a[3] < a[2]) ? 3 : 2;
    float p45 = fminf(a[4], a[5]);  int q45 = (a[5] < a[4]) ? 5 : 4;
    float p67 = fminf(a[6], a[7]);  int q67 = (a[7] < a[6]) ? 7 : 6;
    float pA  = fminf(p01, p23);    int qA  = (p23 < p01) ? q23 : q01;
    float pB  = fminf(p45, p67);    int qB  = (p67 < p45) ? q67 : q45;
    float amin = fminf(pA, pB);     int imin = (pB < pA) ? qB : qA;

    float s = ((a[0] + a[1]) + (a[2] + a[3])) + ((a[4] + a[5]) + (a[6] + a[7]));
    unsigned par = __popc(smask) & 1u;

    float pairDot = a1v + a2v;
    float halfDot = 0.5f * s - (par ? amin : 0.0f);
    bool usePair = pairDot >= halfDot;

    int i = min(i1, i2), j = max(i1, i2);
    int pidx = i * 7 - ((i * (i - 1)) >> 1) + (j - i - 1);
    unsigned si = (smask >> i) & 1u, sj = (smask >> j) & 1u;
    int idxPair = 4 * pidx + 2 * (int)si + (int)sj;

    unsigned rmask = __brev(smask) >> 24;
    unsigned hv = rmask ^ (par << (7 - imin));
    int idxHalf = 112 + (int)(hv >> 1);

    #pragma unroll
    for (int k = 0; k < 8; k++) {
        float sgn = ((smask >> k) & 1u) ? -1.0f : 1.0f;
        float pairRoot = ((k == i1) | (k == i2)) ? sgn : 0.0f;
        float halfRoot = ((hv >> (7 - k)) & 1u) ? -0.5f : 0.5f;
        root_out[k] = usePair ? pairRoot : halfRoot;
    }
    return usePair ? idxPair : idxHalf;
}

__device__ __forceinline__ void qmul(const float q[4], const float p[4], float o[4]) {
    o[0] = q[0]*p[0] - q[1]*p[1] - q[2]*p[2] - q[3]*p[3];
    o[1] = q[0]*p[1] + q[1]*p[0] + q[2]*p[3] - q[3]*p[2];
    o[2] = q[0]*p[2] - q[1]*p[3] + q[2]*p[0] + q[3]*p[1];
    o[3] = q[0]*p[3] + q[1]*p[2] - q[2]*p[1] + q[3]*p[0];
}

// Quantize one row into smem + idx outputs; returns squared error contribution.
__device__ __forceinline__ float quant_row(const float* __restrict__ states,
                                           float* __restrict__ out,
                                           int row, int nrows, size_t off_idx,
                                           float* sp) {
    float x[8];
    const float4* p = reinterpret_cast<const float4*>(states + (size_t)row * 8);
    float4 v0 = p[0], v1 = p[1];
    x[0] = v0.x; x[1] = v0.y; x[2] = v0.z; x[3] = v0.w;
    x[4] = v1.x; x[5] = v1.y; x[6] = v1.z; x[7] = v1.w;

    float res[8], root[8], qsum[8];
    #pragma unroll
    for (int k = 0; k < 8; k++) res[k] = x[k];

    int idx0 = e8_nearest(res, root);
    #pragma unroll
    for (int k = 0; k < 8; k++) { qsum[k] = root[k]; res[k] = x[k] - qsum[k]; }

    int idx1 = e8_nearest(res, root);
    float qe = 0.0f;
    #pragma unroll
    for (int k = 0; k < 8; k++) {
        qsum[k] += root[k];
        float d = x[k] - qsum[k];
        qe += d * d;
        sp[k] = qsum[k];
    }
    out[off_idx + row]                 = (float)idx0;
    out[off_idx + (size_t)nrows + row] = (float)idx1;
    return qe;
}

// Fano alignment for one (state, line); fills pr[8], returns 1-clip(align).
__device__ __forceinline__ float fano_row(const float* __restrict__ base, int sub,
                                          float* __restrict__ align_out, int row,
                                          float pr[8]) {
    int sh = sub * 4;
    int hi = (int)((LI_PACK >> sh) & 7u);
    int hj = (int)((LJ_PACK >> sh) & 7u);
    int hk = (int)((LK_PACK >> sh) & 7u);
    const float* av = base + hi * 8;
    const float* bv = base + hj * 8;
    const float* cv = base + hk * 8;

    float aq[4] = {av[0], av[1], av[2], av[3]};
    float bq[4] = {av[4], av[5], av[6], av[7]};
    float cq[4] = {bv[0], bv[1], bv[2], bv[3]};
    float dq[4] = {bv[4], bv[5], bv[6], bv[7]};
    float dconj[4] = {dq[0], -dq[1], -dq[2], -dq[3]};
    float cconj[4] = {cq[0], -cq[1], -cq[2], -cq[3]};

    float t1[4], t2[4], t3[4], t4[4];
    qmul(aq, cq, t1);
    qmul(dconj, bq, t2);
    qmul(dq, aq, t3);
    qmul(bq, cconj, t4);

    float dot = 0.0f, np2 = 0.0f, nc2 = 0.0f;
    #pragma unroll
    for (int k = 0; k < 4; k++) {
        float plo = t1[k] - t2[k];
        float phi = t3[k] + t4[k];
        float clo = cv[k], chi = cv[4 + k];
        dot += plo * clo + phi * chi;
        np2 += plo * plo + phi * phi;
        nc2 += clo * clo + chi * chi;
        pr[k]     = plo;
        pr[4 + k] = phi;
    }
    float align = dot * rsqrtf(fmaxf(np2 * nc2, 1e-16f));
    align_out[row] = align;
    return 1.0f - fminf(fmaxf(align, -1.0f), 1.0f);
}

template <bool FULL>
__device__ __forceinline__ void fused_body(
        const float* __restrict__ states,
        float* __restrict__ out,
        float* __restrict__ prod_out,
        float* __restrict__ align_out,
        int nrows, size_t off_idx, int rem,
        float* sq, float* nbuf, float& qe, float& fsv) {
    int tid = threadIdx.x;
    int row0 = blockIdx.x * RPB + tid;       // rows tid and tid+224
    int b_local = tid / 7;                   // 224 = 32*7 -> second row: b_local+32, same sub
    int sub     = tid - b_local * 7;

    // ---------------- Phase 1: quantize both rows (independent chains) ---
    if (FULL || tid < rem)
        qe += quant_row(states, out, row0, nrows, off_idx,
                        sq + b_local * SQ_STRIDE + sub * 8);
    if (FULL || (tid + TPB) < rem)
        qe += quant_row(states, out, row0 + TPB, nrows, off_idx,
                        sq + (b_local + 32) * SQ_STRIDE + sub * 8);
    __syncthreads();

    // ------- Coalesced q writeout (4 dense float4 slots per thread) ------
    {
        size_t base_f = (size_t)blockIdx.x * RPB * 8;
        float4* qout = reinterpret_cast<float4*>(out + base_f);
        int rl0 = tid >> 1;
        int bl0 = rl0 / 7;
        int h0  = rl0 - bl0 * 7;
        int k0  = (tid & 1) << 2;
        const float* sp = sq + bl0 * SQ_STRIDE + h0 * 8 + k0;
        #pragma unroll
        for (int it = 0; it < 4; it++) {      // slot s = tid + it*224: bl += 16/it
            if (FULL || ((tid + it * TPB) * 4) < rem * 8)
                qout[tid + it * TPB] = make_float4(sp[0], sp[1], sp[2], sp[3]);
            sp += 16 * SQ_STRIDE;
        }
    }

    // ---------------- Phase 2: Fano for both rows ------------------------
    float pr0[8], pr1[8];
    if (FULL || tid < rem) {
        fsv += fano_row(sq + b_local * SQ_STRIDE, sub, align_out, row0, pr0);
        float* nb = nbuf + tid * 3;
        nb[0] = pr0[0]; nb[1] = pr0[1]; nb[2] = pr0[2];
    }
    if (FULL || (tid + TPB) < rem) {
        fsv += fano_row(sq + (b_local + 32) * SQ_STRIDE, sub, align_out, row0 + TPB, pr1);
        float* nb = nbuf + (tid + TPB) * 3;
        nb[0] = pr1[0]; nb[1] = pr1[1]; nb[2] = pr1[2];
    }
    __syncthreads();

    // ------- Products writeout (gp+3 is 16B aligned; dense STG.128) ------
    {
        float* gp = prod_out + (size_t)blockIdx.x * RPB * 8;
        if (FULL) {
            float4* g4 = reinterpret_cast<float4*>(gp + 3);
            // row rr = tid
            g4[2 * tid] = make_float4(pr0[3], pr0[4], pr0[5], pr0[6]);
            {
                const float* nb = nbuf + (tid + 1) * 3;   // tid+1 < 448 always
                g4[2 * tid + 1] = make_float4(pr0[7], nb[0], nb[1], nb[2]);
            }
            // row rr = tid + 224
            int rr = tid + TPB;
            g4[2 * rr] = make_float4(pr1[3], pr1[4], pr1[5], pr1[6]);
            if (rr < RPB - 1) {
                const float* nb = nbuf + (rr + 1) * 3;
                g4[2 * rr + 1] = make_float4(pr1[7], nb[0], nb[1], nb[2]);
            }
            if (tid == 0)       { gp[0] = pr0[0]; gp[1] = pr0[1]; gp[2] = pr0[2]; }
            if (tid == TPB - 1) { gp[RPB * 8 - 1] = pr1[7]; }
        } else {
            if (tid < rem) {
                float* pw = gp + tid * 8;
                #pragma unroll
                for (int k = 0; k < 8; k++) pw[k] = pr0[k];
            }
            if (tid + TPB < rem) {
                float* pw = gp + (tid + TPB) * 8;
                #pragma unroll
                for (int k = 0; k < 8; k++) pw[k] = pr1[k];
            }
        }
    }
}

__global__ void __launch_bounds__(TPB, 6)
fused_kernel(const float* __restrict__ states,
             float* __restrict__ out,
             float* __restrict__ prod_out,
             float* __restrict__ align_out,
             float* __restrict__ qerr_out,
             float* __restrict__ fano_out,
             int nrows, size_t off_idx,
             double inv_nq, double inv_nf,
             unsigned nblocks) {
    __shared__ float sq[BPB * SQ_STRIDE];   // 64*57*4 = 14592 B
    __shared__ float nbuf[RPB * 3];         // 448*3*4 = 5376 B

    int rem = nrows - blockIdx.x * RPB;
    float qe = 0.0f, fsv = 0.0f;

    if (rem >= RPB) {
        fused_body<true>(states, out, prod_out, align_out,
                         nrows, off_idx, rem, sq, nbuf, qe, fsv);
    } else {
        fused_body<false>(states, out, prod_out, align_out,
                          nrows, off_idx, rem, sq, nbuf, qe, fsv);
    }

    float bq_, bf_;
    blockReduce2F(qe, fsv, bq_, bf_);

    __shared__ bool amLast;
    if (threadIdx.x == 0) {
        atomicAdd(&g_qerr_sum, (double)bq_);
        atomicAdd(&g_fano_sum, (double)bf_);
        __threadfence();
        unsigned done = atomicAdd(&g_count, 1u);
        amLast = (done == nblocks - 1);
    }
    __syncthreads();
    if (amLast && threadIdx.x == 0) {
        double tq = *((volatile double*)&g_qerr_sum);
        double tf = *((volatile double*)&g_fano_sum);
        *qerr_out = (float)(tq * inv_nq);
        double fl = tf * inv_nf * 0.5;
        if (fl < 0.0) fl = 0.0;
        if (fl > 1.0) fl = 1.0;
        *fano_out = (float)fl;
        g_qerr_sum = 0.0;
        g_fano_sum = 0.0;
        g_count = 0;
    }
}

extern "C" void kernel_launch(void* const* d_in, const int* in_sizes, int n_in,
                              void* d_out, int out_size) {
    const float* states = (const float*)d_in[0];
    // d_in[1] = roots; d_in[2..4] = fano line indices (fixed constants, baked in)

    int B = in_sizes[0] / (HH * 8);      // 65536
    int nrows = B * HH;                  // 458752 = 448 * 1024

    float* out = (float*)d_out;
    size_t off_idx   = (size_t)nrows * 8;
    size_t off_qerr  = off_idx + 2 * (size_t)nrows;
    size_t off_prod  = off_qerr + 1;
    size_t off_align = off_prod + (size_t)B * LL * 8;
    size_t off_fano  = off_align + (size_t)B * LL;

    unsigned nblocks = (unsigned)((nrows + RPB - 1) / RPB);   // 1024

    fused_kernel<<<nblocks, TPB>>>(states, out,
                                   out + off_prod, out + off_align,
                                   out + off_qerr, out + off_fano,
                                   nrows, off_idx,
                                   1.0 / ((double)nrows * 8.0),
                                   1.0 / ((double)B * (double)LL),
                                   nblocks);
}